// round 14
// baseline (speedup 1.0000x reference)
#include <cuda_runtime.h>
#include <cuda_fp16.h>
#include <stdint.h>

#define NMAX 100000
#define EMAX 1600000
#define D 64
#define SLOTS 96   // padded bucket capacity; P(in-degree > 96) < 1e-26 for Poisson(16)

// Scratch (static device globals: allocation-free, graph-capturable).
// g_fill starts zero-initialized and is RESET by gather_kernel (lane 0 per
// node) at the end of each launch, so graph replays are deterministic.
__device__ __half g_xsh[(size_t)NMAX * D];          // xs = (x@W)*dinv[row], fp16
__device__ int    g_fill[NMAX];                     // per-node in-degree / slot counter
__device__ float  g_dinv[NMAX];
__device__ int    g_srclist[(size_t)NMAX * SLOTS];  // padded per-dst source buckets

// ---------------------------------------------------------------------------
// K1: bucket fill: pos = fill[dst]++; srclist[dst*SLOTS + pos] = src.
// Replaces deg-count + 3-kernel prefix scan + CSR fill in ONE pass.
// ---------------------------------------------------------------------------
__global__ void fill_kernel(const int* __restrict__ ei, int E)
{
    int e = blockIdx.x * blockDim.x + threadIdx.x;
    if (e < E) {
        int s = __ldg(&ei[e]);
        int d = __ldg(&ei[E + e]);
        int pos = atomicAdd(&g_fill[d], 1);
        if (pos < SLOTS) g_srclist[(size_t)d * SLOTS + pos] = s;
    }
}

// ---------------------------------------------------------------------------
// K2: dinv[i] = rsqrt(deg+1) using the true in-degree in g_fill (not clamped).
// ---------------------------------------------------------------------------
__global__ void dinv_kernel(int n)
{
    int i = blockIdx.x * blockDim.x + threadIdx.x;
    if (i < n) g_dinv[i] = rsqrtf((float)g_fill[i] + 1.0f);
}

// ---------------------------------------------------------------------------
// K3: xsh = fp16( (x@W) * dinv[row] )
// 256 threads, 64 rows/block, 4 rows x 4 cols register blocking,
// k-loop unrolled by 4 with LDS.128 broadcast x-row reads.
// ---------------------------------------------------------------------------
__global__ void __launch_bounds__(256) gemm64_kernel(
    const float* __restrict__ x, const float* __restrict__ W, int n)
{
    __shared__ float  sX[64][68];
    __shared__ float4 sW[64][16];

    const int t = threadIdx.x;
    const int rowBase = blockIdx.x * 64;

    {
        const float4* W4 = (const float4*)W;
        #pragma unroll
        for (int i = 0; i < 4; i++) {
            int idx = t + i * 256;
            sW[idx >> 4][idx & 15] = W4[idx];
        }
    }
    {
        #pragma unroll
        for (int i = 0; i < 4; i++) {
            int idx = t + i * 256;
            int r = idx >> 4, c4 = idx & 15;
            int row = rowBase + r;
            float4 v = make_float4(0.f, 0.f, 0.f, 0.f);
            if (row < n) v = ((const float4*)(x + (size_t)row * D))[c4];
            *(float4*)&sX[r][c4 * 4] = v;
        }
    }
    __syncthreads();

    const int c4 = t & 15;
    const int r0 = t >> 4;

    float4 acc[4];
    #pragma unroll
    for (int r = 0; r < 4; r++) acc[r] = make_float4(0.f, 0.f, 0.f, 0.f);

    #pragma unroll
    for (int k = 0; k < 64; k += 4) {
        float4 w0 = sW[k + 0][c4];
        float4 w1 = sW[k + 1][c4];
        float4 w2 = sW[k + 2][c4];
        float4 w3 = sW[k + 3][c4];
        #pragma unroll
        for (int r = 0; r < 4; r++) {
            float4 xv = *(const float4*)&sX[r0 + 16 * r][k];
            acc[r].x += xv.x * w0.x + xv.y * w1.x + xv.z * w2.x + xv.w * w3.x;
            acc[r].y += xv.x * w0.y + xv.y * w1.y + xv.z * w2.y + xv.w * w3.y;
            acc[r].z += xv.x * w0.z + xv.y * w1.z + xv.z * w2.z + xv.w * w3.z;
            acc[r].w += xv.x * w0.w + xv.y * w1.w + xv.z * w2.w + xv.w * w3.w;
        }
    }

    #pragma unroll
    for (int r = 0; r < 4; r++) {
        int row = rowBase + r0 + 16 * r;
        if (row < n) {
            float di = g_dinv[row];
            __half2* hp = (__half2*)(g_xsh + (size_t)row * D);
            hp[c4 * 2 + 0] = __floats2half2_rn(acc[r].x * di, acc[r].y * di);
            hp[c4 * 2 + 1] = __floats2half2_rn(acc[r].z * di, acc[r].w * di);
        }
    }
}

// ---------------------------------------------------------------------------
// K4: bucket gather, warp per node, MLP=8.
//   out[i] = ( xsh[i] + sum_{s in bucket(i)} xsh[s] ) * dinv[i] + b
// Lane 0 reads the node's count and RESETS g_fill[i] to 0 (replay
// determinism); count is shfl-broadcast. Each source row = one warp-wide
// 128B coalesced load (__half2 per lane); 8 independent rows in flight.
// ---------------------------------------------------------------------------
__global__ void __launch_bounds__(256) gather_kernel(
    const float* __restrict__ b, float* __restrict__ out, int n)
{
    int warp = (int)((blockIdx.x * 256u + threadIdx.x) >> 5);
    int lane = threadIdx.x & 31;
    if (warp >= n) return;
    const int i = warp;

    const __half2* __restrict__ xbase = (const __half2*)g_xsh;

    int cnt = 0;
    if (lane == 0) {
        cnt = g_fill[i];
        g_fill[i] = 0;                     // reset for next graph replay
    }
    cnt = __shfl_sync(0xFFFFFFFFu, cnt, 0);
    cnt = min(cnt, SLOTS);
    float di = g_dinv[i];

    const int* __restrict__ slot = g_srclist + (size_t)i * SLOTS;

    // self message (fp16 row); row stride in __half2 units = D/2 = 32
    float2 acc = __half22float2(__ldg(xbase + (size_t)i * 32 + lane));

    for (int k0 = 0; k0 < cnt; k0 += 32) {
        int m = min(cnt - k0, 32);
        int sl = (lane < m) ? __ldg(&slot[k0 + lane]) : 0;

        int kk = 0;
        for (; kk + 8 <= m; kk += 8) {
            int s0 = __shfl_sync(0xFFFFFFFFu, sl, kk + 0);
            int s1 = __shfl_sync(0xFFFFFFFFu, sl, kk + 1);
            int s2 = __shfl_sync(0xFFFFFFFFu, sl, kk + 2);
            int s3 = __shfl_sync(0xFFFFFFFFu, sl, kk + 3);
            int s4 = __shfl_sync(0xFFFFFFFFu, sl, kk + 4);
            int s5 = __shfl_sync(0xFFFFFFFFu, sl, kk + 5);
            int s6 = __shfl_sync(0xFFFFFFFFu, sl, kk + 6);
            int s7 = __shfl_sync(0xFFFFFFFFu, sl, kk + 7);
            // 8 independent 128B row loads in flight
            __half2 v0 = __ldg(xbase + (size_t)s0 * 32 + lane);
            __half2 v1 = __ldg(xbase + (size_t)s1 * 32 + lane);
            __half2 v2 = __ldg(xbase + (size_t)s2 * 32 + lane);
            __half2 v3 = __ldg(xbase + (size_t)s3 * 32 + lane);
            __half2 v4 = __ldg(xbase + (size_t)s4 * 32 + lane);
            __half2 v5 = __ldg(xbase + (size_t)s5 * 32 + lane);
            __half2 v6 = __ldg(xbase + (size_t)s6 * 32 + lane);
            __half2 v7 = __ldg(xbase + (size_t)s7 * 32 + lane);
            float2 f;
            f = __half22float2(v0); acc.x += f.x; acc.y += f.y;
            f = __half22float2(v1); acc.x += f.x; acc.y += f.y;
            f = __half22float2(v2); acc.x += f.x; acc.y += f.y;
            f = __half22float2(v3); acc.x += f.x; acc.y += f.y;
            f = __half22float2(v4); acc.x += f.x; acc.y += f.y;
            f = __half22float2(v5); acc.x += f.x; acc.y += f.y;
            f = __half22float2(v6); acc.x += f.x; acc.y += f.y;
            f = __half22float2(v7); acc.x += f.x; acc.y += f.y;
        }
        for (; kk < m; kk++) {
            int s = __shfl_sync(0xFFFFFFFFu, sl, kk);
            float2 f = __half22float2(__ldg(xbase + (size_t)s * 32 + lane));
            acc.x += f.x; acc.y += f.y;
        }
    }

    float2 bb = *((const float2*)b + lane);
    float2 o;
    o.x = acc.x * di + bb.x;
    o.y = acc.y * di + bb.y;
    *((float2*)(out + (size_t)i * D) + lane) = o;
}

// ---------------------------------------------------------------------------
// Launch
// Inputs (metadata order): x [n*64] f32, edge_index [2*E] int32, W [64*64] f32,
//                          b [64] f32. Output: [n*64] f32.
// 4 launches: fill, dinv, gemm, gather.
// ---------------------------------------------------------------------------
extern "C" void kernel_launch(void* const* d_in, const int* in_sizes, int n_in,
                              void* d_out, int out_size)
{
    const float* x  = (const float*)d_in[0];
    const int*   ei = (const int*)d_in[1];
    const float* W  = (const float*)d_in[2];
    const float* b  = (const float*)d_in[3];
    float*       out = (float*)d_out;

    const int n = in_sizes[0] / D;       // 100000
    const int E = in_sizes[1] / 2;       // 1600000

    fill_kernel<<<(E + 255) / 256, 256>>>(ei, E);
    dinv_kernel<<<(n + 255) / 256, 256>>>(n);
    gemm64_kernel<<<(n + 63) / 64, 256>>>(x, W, n);
    {
        int total = n * 32;                      // 1 warp per node
        gather_kernel<<<(total + 255) / 256, 256>>>(b, out, n);
    }
}

// round 15
// speedup vs baseline: 1.5481x; 1.5481x over previous
#include <cuda_runtime.h>
#include <cuda_fp16.h>
#include <stdint.h>

#define NMAX 100000
#define EMAX 1600000
#define D 64
#define NPART 512   // >= ceil(NMAX/256) = 391

// Scratch (static device globals: allocation-free, graph-capturable).
// g_degi starts zero-initialized and is RESET in scan3 each launch, so graph
// replays are deterministic. g_fill is rewritten from the scan each launch.
__device__ __half g_xsh[(size_t)NMAX * D];  // xs = (x@W)*dinv[row], fp16
__device__ int    g_degi[NMAX];
__device__ float  g_dinv[NMAX];
__device__ int    g_rowstart[NMAX + 1];
__device__ int    g_fill[NMAX];
__device__ int    g_srclist[EMAX];
__device__ int    g_part[NPART];
__device__ int    g_blockoff[NPART];

// ---------------------------------------------------------------------------
// K1: in-degree histogram. 1 edge/thread: max cross-warp MLP on the RED path.
// ---------------------------------------------------------------------------
__global__ void deg_count_kernel(const int* __restrict__ dst, int E)
{
    int e = blockIdx.x * blockDim.x + threadIdx.x;
    if (e < E) atomicAdd(&g_degi[__ldg(&dst[e])], 1);
}

// ---------------------------------------------------------------------------
// K2a: per-block partial sums of degi (256 elements per block)
// ---------------------------------------------------------------------------
__global__ void __launch_bounds__(256) scan1_kernel(int n)
{
    __shared__ int sd[256];
    int t = threadIdx.x;
    int i = blockIdx.x * 256 + t;
    sd[t] = (i < n) ? g_degi[i] : 0;
    __syncthreads();
    #pragma unroll
    for (int ofs = 128; ofs > 0; ofs >>= 1) {
        if (t < ofs) sd[t] += sd[t + ofs];
        __syncthreads();
    }
    if (t == 0) g_part[blockIdx.x] = sd[0];
}

// ---------------------------------------------------------------------------
// K2b: single-block exclusive scan of the partials -> g_blockoff
// ---------------------------------------------------------------------------
__global__ void __launch_bounds__(512) scan2_kernel(int nblocks)
{
    __shared__ int sp[512];
    int t = threadIdx.x;
    int v0 = (t < nblocks) ? g_part[t] : 0;
    sp[t] = v0;
    __syncthreads();
    int v = v0;
    #pragma unroll
    for (int ofs = 1; ofs < 512; ofs <<= 1) {
        int u = (t >= ofs) ? sp[t - ofs] : 0;
        __syncthreads();
        v += u;
        sp[t] = v;
        __syncthreads();
    }
    if (t < nblocks) g_blockoff[t] = v - v0;   // exclusive
}

// ---------------------------------------------------------------------------
// K2c: block-local exclusive scan + offsets -> rowstart/fill; dinv; deg reset.
// ---------------------------------------------------------------------------
__global__ void __launch_bounds__(256) scan3_kernel(int n, int E)
{
    __shared__ int sd[256];
    int t = threadIdx.x;
    int i = blockIdx.x * 256 + t;
    int dg = (i < n) ? g_degi[i] : 0;
    sd[t] = dg;
    __syncthreads();
    int v = dg;
    #pragma unroll
    for (int ofs = 1; ofs < 256; ofs <<= 1) {
        int u = (t >= ofs) ? sd[t - ofs] : 0;
        __syncthreads();
        v += u;
        sd[t] = v;
        __syncthreads();
    }
    if (i < n) {
        int rs = g_blockoff[blockIdx.x] + (v - dg);  // global exclusive prefix
        g_rowstart[i] = rs;
        g_fill[i]     = rs;
        g_dinv[i]     = rsqrtf((float)(dg + 1));
        g_degi[i]     = 0;                  // reset for next graph replay
    }
    if (blockIdx.x == 0 && t == 0) g_rowstart[n] = E;
}

// ---------------------------------------------------------------------------
// K3: CSR fill: srclist[fill[dst]++] = src. 1 edge/thread.
// ---------------------------------------------------------------------------
__global__ void fill_kernel(const int* __restrict__ ei, int E)
{
    int e = blockIdx.x * blockDim.x + threadIdx.x;
    if (e < E) {
        int s = __ldg(&ei[e]);
        int d = __ldg(&ei[E + e]);
        int pos = atomicAdd(&g_fill[d], 1);
        g_srclist[pos] = s;
    }
}

// ---------------------------------------------------------------------------
// K4: xsh = fp16( (x@W) * dinv[row] )
// 256 threads, 64 rows/block, 4 rows x 4 cols register blocking,
// k-loop unrolled by 4 with LDS.128 broadcast x-row reads.
// ---------------------------------------------------------------------------
__global__ void __launch_bounds__(256) gemm64_kernel(
    const float* __restrict__ x, const float* __restrict__ W, int n)
{
    __shared__ float  sX[64][68];
    __shared__ float4 sW[64][16];

    const int t = threadIdx.x;
    const int rowBase = blockIdx.x * 64;

    {
        const float4* W4 = (const float4*)W;
        #pragma unroll
        for (int i = 0; i < 4; i++) {
            int idx = t + i * 256;
            sW[idx >> 4][idx & 15] = W4[idx];
        }
    }
    {
        #pragma unroll
        for (int i = 0; i < 4; i++) {
            int idx = t + i * 256;
            int r = idx >> 4, c4 = idx & 15;
            int row = rowBase + r;
            float4 v = make_float4(0.f, 0.f, 0.f, 0.f);
            if (row < n) v = ((const float4*)(x + (size_t)row * D))[c4];
            *(float4*)&sX[r][c4 * 4] = v;
        }
    }
    __syncthreads();

    const int c4 = t & 15;
    const int r0 = t >> 4;

    float4 acc[4];
    #pragma unroll
    for (int r = 0; r < 4; r++) acc[r] = make_float4(0.f, 0.f, 0.f, 0.f);

    #pragma unroll
    for (int k = 0; k < 64; k += 4) {
        float4 w0 = sW[k + 0][c4];
        float4 w1 = sW[k + 1][c4];
        float4 w2 = sW[k + 2][c4];
        float4 w3 = sW[k + 3][c4];
        #pragma unroll
        for (int r = 0; r < 4; r++) {
            float4 xv = *(const float4*)&sX[r0 + 16 * r][k];
            acc[r].x += xv.x * w0.x + xv.y * w1.x + xv.z * w2.x + xv.w * w3.x;
            acc[r].y += xv.x * w0.y + xv.y * w1.y + xv.z * w2.y + xv.w * w3.y;
            acc[r].z += xv.x * w0.z + xv.y * w1.z + xv.z * w2.z + xv.w * w3.z;
            acc[r].w += xv.x * w0.w + xv.y * w1.w + xv.z * w2.w + xv.w * w3.w;
        }
    }

    #pragma unroll
    for (int r = 0; r < 4; r++) {
        int row = rowBase + r0 + 16 * r;
        if (row < n) {
            float di = g_dinv[row];
            __half2* hp = (__half2*)(g_xsh + (size_t)row * D);
            hp[c4 * 2 + 0] = __floats2half2_rn(acc[r].x * di, acc[r].y * di);
            hp[c4 * 2 + 1] = __floats2half2_rn(acc[r].z * di, acc[r].w * di);
        }
    }
}

// ---------------------------------------------------------------------------
// K5: CSR gather, warp per node, 16 independent row loads in flight.
//   out[i] = ( xsh[i] + sum_{s in in(i)} xsh[s] ) * dinv[i] + b
// Each lane owns 2 dims (one __half2 / 4B per row load -> 128B/warp, 1 line).
// cnt is warp-uniform: all branches divergence-free.
// ---------------------------------------------------------------------------
__global__ void __launch_bounds__(256) gather_kernel(
    const float* __restrict__ b, float* __restrict__ out, int n)
{
    int warp = (int)((blockIdx.x * 256u + threadIdx.x) >> 5);
    int lane = threadIdx.x & 31;
    if (warp >= n) return;
    const int i = warp;

    const __half2* __restrict__ xbase = (const __half2*)g_xsh;

    int start = g_rowstart[i];
    int cnt   = g_rowstart[i + 1] - start;
    float di  = g_dinv[i];

    // self message (fp16 row); row stride in __half2 units = D/2 = 32
    float2 acc = __half22float2(__ldg(xbase + (size_t)i * 32 + lane));

    for (int k0 = 0; k0 < cnt; k0 += 32) {
        int m = min(cnt - k0, 32);
        int sl = (lane < m) ? __ldg(&g_srclist[start + k0 + lane]) : 0;

        int kk = 0;
        for (; kk + 16 <= m; kk += 16) {
            int s0  = __shfl_sync(0xFFFFFFFFu, sl, kk + 0);
            int s1  = __shfl_sync(0xFFFFFFFFu, sl, kk + 1);
            int s2  = __shfl_sync(0xFFFFFFFFu, sl, kk + 2);
            int s3  = __shfl_sync(0xFFFFFFFFu, sl, kk + 3);
            int s4  = __shfl_sync(0xFFFFFFFFu, sl, kk + 4);
            int s5  = __shfl_sync(0xFFFFFFFFu, sl, kk + 5);
            int s6  = __shfl_sync(0xFFFFFFFFu, sl, kk + 6);
            int s7  = __shfl_sync(0xFFFFFFFFu, sl, kk + 7);
            int s8  = __shfl_sync(0xFFFFFFFFu, sl, kk + 8);
            int s9  = __shfl_sync(0xFFFFFFFFu, sl, kk + 9);
            int s10 = __shfl_sync(0xFFFFFFFFu, sl, kk + 10);
            int s11 = __shfl_sync(0xFFFFFFFFu, sl, kk + 11);
            int s12 = __shfl_sync(0xFFFFFFFFu, sl, kk + 12);
            int s13 = __shfl_sync(0xFFFFFFFFu, sl, kk + 13);
            int s14 = __shfl_sync(0xFFFFFFFFu, sl, kk + 14);
            int s15 = __shfl_sync(0xFFFFFFFFu, sl, kk + 15);
            // 16 independent 128B row loads in flight
            __half2 v0  = __ldg(xbase + (size_t)s0  * 32 + lane);
            __half2 v1  = __ldg(xbase + (size_t)s1  * 32 + lane);
            __half2 v2  = __ldg(xbase + (size_t)s2  * 32 + lane);
            __half2 v3  = __ldg(xbase + (size_t)s3  * 32 + lane);
            __half2 v4  = __ldg(xbase + (size_t)s4  * 32 + lane);
            __half2 v5  = __ldg(xbase + (size_t)s5  * 32 + lane);
            __half2 v6  = __ldg(xbase + (size_t)s6  * 32 + lane);
            __half2 v7  = __ldg(xbase + (size_t)s7  * 32 + lane);
            __half2 v8  = __ldg(xbase + (size_t)s8  * 32 + lane);
            __half2 v9  = __ldg(xbase + (size_t)s9  * 32 + lane);
            __half2 v10 = __ldg(xbase + (size_t)s10 * 32 + lane);
            __half2 v11 = __ldg(xbase + (size_t)s11 * 32 + lane);
            __half2 v12 = __ldg(xbase + (size_t)s12 * 32 + lane);
            __half2 v13 = __ldg(xbase + (size_t)s13 * 32 + lane);
            __half2 v14 = __ldg(xbase + (size_t)s14 * 32 + lane);
            __half2 v15 = __ldg(xbase + (size_t)s15 * 32 + lane);
            float2 f;
            f = __half22float2(v0);  acc.x += f.x; acc.y += f.y;
            f = __half22float2(v1);  acc.x += f.x; acc.y += f.y;
            f = __half22float2(v2);  acc.x += f.x; acc.y += f.y;
            f = __half22float2(v3);  acc.x += f.x; acc.y += f.y;
            f = __half22float2(v4);  acc.x += f.x; acc.y += f.y;
            f = __half22float2(v5);  acc.x += f.x; acc.y += f.y;
            f = __half22float2(v6);  acc.x += f.x; acc.y += f.y;
            f = __half22float2(v7);  acc.x += f.x; acc.y += f.y;
            f = __half22float2(v8);  acc.x += f.x; acc.y += f.y;
            f = __half22float2(v9);  acc.x += f.x; acc.y += f.y;
            f = __half22float2(v10); acc.x += f.x; acc.y += f.y;
            f = __half22float2(v11); acc.x += f.x; acc.y += f.y;
            f = __half22float2(v12); acc.x += f.x; acc.y += f.y;
            f = __half22float2(v13); acc.x += f.x; acc.y += f.y;
            f = __half22float2(v14); acc.x += f.x; acc.y += f.y;
            f = __half22float2(v15); acc.x += f.x; acc.y += f.y;
        }
        for (; kk + 4 <= m; kk += 4) {
            int s0 = __shfl_sync(0xFFFFFFFFu, sl, kk + 0);
            int s1 = __shfl_sync(0xFFFFFFFFu, sl, kk + 1);
            int s2 = __shfl_sync(0xFFFFFFFFu, sl, kk + 2);
            int s3 = __shfl_sync(0xFFFFFFFFu, sl, kk + 3);
            __half2 v0 = __ldg(xbase + (size_t)s0 * 32 + lane);
            __half2 v1 = __ldg(xbase + (size_t)s1 * 32 + lane);
            __half2 v2 = __ldg(xbase + (size_t)s2 * 32 + lane);
            __half2 v3 = __ldg(xbase + (size_t)s3 * 32 + lane);
            float2 f;
            f = __half22float2(v0); acc.x += f.x; acc.y += f.y;
            f = __half22float2(v1); acc.x += f.x; acc.y += f.y;
            f = __half22float2(v2); acc.x += f.x; acc.y += f.y;
            f = __half22float2(v3); acc.x += f.x; acc.y += f.y;
        }
        for (; kk < m; kk++) {
            int s = __shfl_sync(0xFFFFFFFFu, sl, kk);
            float2 f = __half22float2(__ldg(xbase + (size_t)s * 32 + lane));
            acc.x += f.x; acc.y += f.y;
        }
    }

    float2 bb = *((const float2*)b + lane);
    float2 o;
    o.x = acc.x * di + bb.x;
    o.y = acc.y * di + bb.y;
    *((float2*)(out + (size_t)i * D) + lane) = o;
}

// ---------------------------------------------------------------------------
// Launch
// Inputs (metadata order): x [n*64] f32, edge_index [2*E] int32, W [64*64] f32,
//                          b [64] f32. Output: [n*64] f32.
// 7 launches: deg, scan1, scan2, scan3, fill, gemm, gather.
// ---------------------------------------------------------------------------
extern "C" void kernel_launch(void* const* d_in, const int* in_sizes, int n_in,
                              void* d_out, int out_size)
{
    const float* x  = (const float*)d_in[0];
    const int*   ei = (const int*)d_in[1];
    const float* W  = (const float*)d_in[2];
    const float* b  = (const float*)d_in[3];
    float*       out = (float*)d_out;

    const int n = in_sizes[0] / D;       // 100000
    const int E = in_sizes[1] / 2;       // 1600000
    const int nblocks = (n + 255) / 256; // 391

    deg_count_kernel<<<(E + 255) / 256, 256>>>(ei + E, E);
    scan1_kernel<<<nblocks, 256>>>(n);
    scan2_kernel<<<1, 512>>>(nblocks);
    scan3_kernel<<<nblocks, 256>>>(n, E);
    fill_kernel<<<(E + 255) / 256, 256>>>(ei, E);
    gemm64_kernel<<<(n + 63) / 64, 256>>>(x, W, n);
    {
        int total = n * 32;                      // 1 warp per node
        gather_kernel<<<(total + 255) / 256, 256>>>(b, out, n);
    }
}

// round 16
// speedup vs baseline: 1.6122x; 1.0415x over previous
#include <cuda_runtime.h>
#include <cuda_fp16.h>
#include <stdint.h>

#define NMAX 100000
#define EMAX 1600000
#define D 64
#define NPART 512   // >= ceil(NMAX/256) = 391

// Scratch (static device globals: allocation-free, graph-capturable).
// g_degi starts zero-initialized and is RESET in scan3 each launch, so graph
// replays are deterministic. g_fill is rewritten from the scan each launch.
__device__ __half g_xsh[(size_t)NMAX * D];  // xs = (x@W)*dinv[row], fp16
__device__ int    g_degi[NMAX];
__device__ float  g_dinv[NMAX];
__device__ int    g_rowstart[NMAX + 1];
__device__ int    g_fill[NMAX];
__device__ int    g_srclist[EMAX];
__device__ int    g_part[NPART];
__device__ int    g_blockoff[NPART];

// ---------------------------------------------------------------------------
// K1: in-degree histogram. 2 edges/thread via int2 (E is even; tail guarded).
// ---------------------------------------------------------------------------
__global__ void deg_count_kernel(const int* __restrict__ dst, int E)
{
    int g = blockIdx.x * blockDim.x + threadIdx.x;
    int e0 = 2 * g;
    if (e0 + 1 < E) {
        int2 dd = *(const int2*)&dst[e0];
        atomicAdd(&g_degi[dd.x], 1);
        atomicAdd(&g_degi[dd.y], 1);
    } else if (e0 < E) {
        atomicAdd(&g_degi[__ldg(&dst[e0])], 1);
    }
}

// ---------------------------------------------------------------------------
// K2a: per-block partial sums of degi (256 elements per block)
// ---------------------------------------------------------------------------
__global__ void __launch_bounds__(256) scan1_kernel(int n)
{
    __shared__ int sd[256];
    int t = threadIdx.x;
    int i = blockIdx.x * 256 + t;
    sd[t] = (i < n) ? g_degi[i] : 0;
    __syncthreads();
    #pragma unroll
    for (int ofs = 128; ofs > 0; ofs >>= 1) {
        if (t < ofs) sd[t] += sd[t + ofs];
        __syncthreads();
    }
    if (t == 0) g_part[blockIdx.x] = sd[0];
}

// ---------------------------------------------------------------------------
// K2b: single-block exclusive scan of the partials -> g_blockoff
// ---------------------------------------------------------------------------
__global__ void __launch_bounds__(512) scan2_kernel(int nblocks)
{
    __shared__ int sp[512];
    int t = threadIdx.x;
    int v0 = (t < nblocks) ? g_part[t] : 0;
    sp[t] = v0;
    __syncthreads();
    int v = v0;
    #pragma unroll
    for (int ofs = 1; ofs < 512; ofs <<= 1) {
        int u = (t >= ofs) ? sp[t - ofs] : 0;
        __syncthreads();
        v += u;
        sp[t] = v;
        __syncthreads();
    }
    if (t < nblocks) g_blockoff[t] = v - v0;   // exclusive
}

// ---------------------------------------------------------------------------
// K2c: block-local exclusive scan + offsets -> rowstart/fill; dinv; deg reset.
// ---------------------------------------------------------------------------
__global__ void __launch_bounds__(256) scan3_kernel(int n, int E)
{
    __shared__ int sd[256];
    int t = threadIdx.x;
    int i = blockIdx.x * 256 + t;
    int dg = (i < n) ? g_degi[i] : 0;
    sd[t] = dg;
    __syncthreads();
    int v = dg;
    #pragma unroll
    for (int ofs = 1; ofs < 256; ofs <<= 1) {
        int u = (t >= ofs) ? sd[t - ofs] : 0;
        __syncthreads();
        v += u;
        sd[t] = v;
        __syncthreads();
    }
    if (i < n) {
        int rs = g_blockoff[blockIdx.x] + (v - dg);  // global exclusive prefix
        g_rowstart[i] = rs;
        g_fill[i]     = rs;
        g_dinv[i]     = rsqrtf((float)(dg + 1));
        g_degi[i]     = 0;                  // reset for next graph replay
    }
    if (blockIdx.x == 0 && t == 0) g_rowstart[n] = E;
}

// ---------------------------------------------------------------------------
// K3: CSR fill: srclist[fill[dst]++] = src. 2 edges/thread via int2.
// ---------------------------------------------------------------------------
__global__ void fill_kernel(const int* __restrict__ ei, int E)
{
    int g = blockIdx.x * blockDim.x + threadIdx.x;
    int e0 = 2 * g;
    if (e0 + 1 < E) {
        int2 ss = *(const int2*)&ei[e0];
        int2 dd = *(const int2*)&ei[E + e0];
        int p0 = atomicAdd(&g_fill[dd.x], 1);
        int p1 = atomicAdd(&g_fill[dd.y], 1);
        g_srclist[p0] = ss.x;
        g_srclist[p1] = ss.y;
    } else if (e0 < E) {
        int s = __ldg(&ei[e0]);
        int d = __ldg(&ei[E + e0]);
        int pos = atomicAdd(&g_fill[d], 1);
        g_srclist[pos] = s;
    }
}

// ---------------------------------------------------------------------------
// K4: xsh = fp16( (x@W) * dinv[row] )
// 256 threads, 64 rows/block, 4 rows x 4 cols register blocking,
// k-loop unrolled by 4 with LDS.128 broadcast x-row reads.
// ---------------------------------------------------------------------------
__global__ void __launch_bounds__(256) gemm64_kernel(
    const float* __restrict__ x, const float* __restrict__ W, int n)
{
    __shared__ float  sX[64][68];
    __shared__ float4 sW[64][16];

    const int t = threadIdx.x;
    const int rowBase = blockIdx.x * 64;

    {
        const float4* W4 = (const float4*)W;
        #pragma unroll
        for (int i = 0; i < 4; i++) {
            int idx = t + i * 256;
            sW[idx >> 4][idx & 15] = W4[idx];
        }
    }
    {
        #pragma unroll
        for (int i = 0; i < 4; i++) {
            int idx = t + i * 256;
            int r = idx >> 4, c4 = idx & 15;
            int row = rowBase + r;
            float4 v = make_float4(0.f, 0.f, 0.f, 0.f);
            if (row < n) v = ((const float4*)(x + (size_t)row * D))[c4];
            *(float4*)&sX[r][c4 * 4] = v;
        }
    }
    __syncthreads();

    const int c4 = t & 15;
    const int r0 = t >> 4;

    float4 acc[4];
    #pragma unroll
    for (int r = 0; r < 4; r++) acc[r] = make_float4(0.f, 0.f, 0.f, 0.f);

    #pragma unroll
    for (int k = 0; k < 64; k += 4) {
        float4 w0 = sW[k + 0][c4];
        float4 w1 = sW[k + 1][c4];
        float4 w2 = sW[k + 2][c4];
        float4 w3 = sW[k + 3][c4];
        #pragma unroll
        for (int r = 0; r < 4; r++) {
            float4 xv = *(const float4*)&sX[r0 + 16 * r][k];
            acc[r].x += xv.x * w0.x + xv.y * w1.x + xv.z * w2.x + xv.w * w3.x;
            acc[r].y += xv.x * w0.y + xv.y * w1.y + xv.z * w2.y + xv.w * w3.y;
            acc[r].z += xv.x * w0.z + xv.y * w1.z + xv.z * w2.z + xv.w * w3.z;
            acc[r].w += xv.x * w0.w + xv.y * w1.w + xv.z * w2.w + xv.w * w3.w;
        }
    }

    #pragma unroll
    for (int r = 0; r < 4; r++) {
        int row = rowBase + r0 + 16 * r;
        if (row < n) {
            float di = g_dinv[row];
            __half2* hp = (__half2*)(g_xsh + (size_t)row * D);
            hp[c4 * 2 + 0] = __floats2half2_rn(acc[r].x * di, acc[r].y * di);
            hp[c4 * 2 + 1] = __floats2half2_rn(acc[r].z * di, acc[r].w * di);
        }
    }
}

// ---------------------------------------------------------------------------
// K5: CSR gather, warp per node, MLP=8 (proven best config).
//   out[i] = ( xsh[i] + sum_{s in in(i)} xsh[s] ) * dinv[i] + b
// Each lane owns 2 dims (one __half2 / 4B per row load -> 128B/warp, 1 line).
// cnt is warp-uniform: all branches divergence-free.
// ---------------------------------------------------------------------------
__global__ void __launch_bounds__(256) gather_kernel(
    const float* __restrict__ b, float* __restrict__ out, int n)
{
    int warp = (int)((blockIdx.x * 256u + threadIdx.x) >> 5);
    int lane = threadIdx.x & 31;
    if (warp >= n) return;
    const int i = warp;

    const __half2* __restrict__ xbase = (const __half2*)g_xsh;

    int start = g_rowstart[i];
    int cnt   = g_rowstart[i + 1] - start;
    float di  = g_dinv[i];

    // self message (fp16 row); row stride in __half2 units = D/2 = 32
    float2 acc = __half22float2(__ldg(xbase + (size_t)i * 32 + lane));

    for (int k0 = 0; k0 < cnt; k0 += 32) {
        int m = min(cnt - k0, 32);
        int sl = (lane < m) ? __ldg(&g_srclist[start + k0 + lane]) : 0;

        int kk = 0;
        for (; kk + 8 <= m; kk += 8) {
            int s0 = __shfl_sync(0xFFFFFFFFu, sl, kk + 0);
            int s1 = __shfl_sync(0xFFFFFFFFu, sl, kk + 1);
            int s2 = __shfl_sync(0xFFFFFFFFu, sl, kk + 2);
            int s3 = __shfl_sync(0xFFFFFFFFu, sl, kk + 3);
            int s4 = __shfl_sync(0xFFFFFFFFu, sl, kk + 4);
            int s5 = __shfl_sync(0xFFFFFFFFu, sl, kk + 5);
            int s6 = __shfl_sync(0xFFFFFFFFu, sl, kk + 6);
            int s7 = __shfl_sync(0xFFFFFFFFu, sl, kk + 7);
            // 8 independent 128B row loads in flight
            __half2 v0 = __ldg(xbase + (size_t)s0 * 32 + lane);
            __half2 v1 = __ldg(xbase + (size_t)s1 * 32 + lane);
            __half2 v2 = __ldg(xbase + (size_t)s2 * 32 + lane);
            __half2 v3 = __ldg(xbase + (size_t)s3 * 32 + lane);
            __half2 v4 = __ldg(xbase + (size_t)s4 * 32 + lane);
            __half2 v5 = __ldg(xbase + (size_t)s5 * 32 + lane);
            __half2 v6 = __ldg(xbase + (size_t)s6 * 32 + lane);
            __half2 v7 = __ldg(xbase + (size_t)s7 * 32 + lane);
            float2 f;
            f = __half22float2(v0); acc.x += f.x; acc.y += f.y;
            f = __half22float2(v1); acc.x += f.x; acc.y += f.y;
            f = __half22float2(v2); acc.x += f.x; acc.y += f.y;
            f = __half22float2(v3); acc.x += f.x; acc.y += f.y;
            f = __half22float2(v4); acc.x += f.x; acc.y += f.y;
            f = __half22float2(v5); acc.x += f.x; acc.y += f.y;
            f = __half22float2(v6); acc.x += f.x; acc.y += f.y;
            f = __half22float2(v7); acc.x += f.x; acc.y += f.y;
        }
        for (; kk < m; kk++) {
            int s = __shfl_sync(0xFFFFFFFFu, sl, kk);
            float2 f = __half22float2(__ldg(xbase + (size_t)s * 32 + lane));
            acc.x += f.x; acc.y += f.y;
        }
    }

    float2 bb = *((const float2*)b + lane);
    float2 o;
    o.x = acc.x * di + bb.x;
    o.y = acc.y * di + bb.y;
    *((float2*)(out + (size_t)i * D) + lane) = o;
}

// ---------------------------------------------------------------------------
// Launch
// Inputs (metadata order): x [n*64] f32, edge_index [2*E] int32, W [64*64] f32,
//                          b [64] f32. Output: [n*64] f32.
// 7 launches: deg, scan1, scan2, scan3, fill, gemm, gather.
// ---------------------------------------------------------------------------
extern "C" void kernel_launch(void* const* d_in, const int* in_sizes, int n_in,
                              void* d_out, int out_size)
{
    const float* x  = (const float*)d_in[0];
    const int*   ei = (const int*)d_in[1];
    const float* W  = (const float*)d_in[2];
    const float* b  = (const float*)d_in[3];
    float*       out = (float*)d_out;

    const int n = in_sizes[0] / D;       // 100000
    const int E = in_sizes[1] / 2;       // 1600000
    const int nblocks = (n + 255) / 256; // 391

    {
        int pairs = (E + 1) / 2;
        deg_count_kernel<<<(pairs + 255) / 256, 256>>>(ei + E, E);
    }
    scan1_kernel<<<nblocks, 256>>>(n);
    scan2_kernel<<<1, 512>>>(nblocks);
    scan3_kernel<<<nblocks, 256>>>(n, E);
    {
        int pairs = (E + 1) / 2;
        fill_kernel<<<(pairs + 255) / 256, 256>>>(ei, E);
    }
    gemm64_kernel<<<(n + 63) / 64, 256>>>(x, W, n);
    {
        int total = n * 32;                      // 1 warp per node
        gather_kernel<<<(total + 255) / 256, 256>>>(b, out, n);
    }
}

// round 17
// speedup vs baseline: 1.7174x; 1.0652x over previous
#include <cuda_runtime.h>
#include <cuda_fp16.h>
#include <stdint.h>

#define NMAX 100000
#define EMAX 1600000
#define D 64
#define NPART 512   // >= ceil(NMAX/256) = 391

// Scratch (static device globals: allocation-free, graph-capturable).
// g_degi starts zero-initialized and is RESET in scan3 each launch, so graph
// replays are deterministic. g_fill is rewritten from the scan each launch.
__device__ __half g_xsh[(size_t)NMAX * D];  // xs = (x@W)*dinv[row], fp16
__device__ int    g_degi[NMAX];
__device__ float  g_dinv[NMAX];
__device__ int    g_rowstart[NMAX + 1];
__device__ int    g_fill[NMAX];
__device__ int    g_srclist[EMAX];
__device__ int    g_part[NPART];

// ---------------------------------------------------------------------------
// K1: in-degree histogram. 2 edges/thread via int2.
// ---------------------------------------------------------------------------
__global__ void deg_count_kernel(const int* __restrict__ dst, int E)
{
    int g = blockIdx.x * blockDim.x + threadIdx.x;
    int e0 = 2 * g;
    if (e0 + 1 < E) {
        int2 dd = *(const int2*)&dst[e0];
        atomicAdd(&g_degi[dd.x], 1);
        atomicAdd(&g_degi[dd.y], 1);
    } else if (e0 < E) {
        atomicAdd(&g_degi[__ldg(&dst[e0])], 1);
    }
}

// ---------------------------------------------------------------------------
// K2a: per-block partial sums of degi (256 elements per block)
// ---------------------------------------------------------------------------
__global__ void __launch_bounds__(256) scan1_kernel(int n)
{
    __shared__ int sd[256];
    int t = threadIdx.x;
    int i = blockIdx.x * 256 + t;
    sd[t] = (i < n) ? g_degi[i] : 0;
    __syncthreads();
    #pragma unroll
    for (int ofs = 128; ofs > 0; ofs >>= 1) {
        if (t < ofs) sd[t] += sd[t + ofs];
        __syncthreads();
    }
    if (t == 0) g_part[blockIdx.x] = sd[0];
}

// ---------------------------------------------------------------------------
// K2b: per-block: compute own offset from g_part directly (replaces the old
// single-block scan2), then block-local exclusive scan ->
// rowstart/fill; dinv; deg reset for graph-replay determinism.
// ---------------------------------------------------------------------------
__global__ void __launch_bounds__(256) scan3_kernel(int n, int E)
{
    __shared__ int sd[256];
    __shared__ int soff;
    int t   = threadIdx.x;
    int bid = blockIdx.x;

    // Block offset: sum of partials of all earlier blocks (<= 391 ints).
    int local = 0;
    for (int j = t; j < bid; j += 256) local += g_part[j];
    sd[t] = local;
    __syncthreads();
    #pragma unroll
    for (int ofs = 128; ofs > 0; ofs >>= 1) {
        if (t < ofs) sd[t] += sd[t + ofs];
        __syncthreads();
    }
    if (t == 0) soff = sd[0];
    __syncthreads();

    // Block-local inclusive scan of degrees.
    int i = bid * 256 + t;
    int dg = (i < n) ? g_degi[i] : 0;
    sd[t] = dg;
    __syncthreads();
    int v = dg;
    #pragma unroll
    for (int ofs = 1; ofs < 256; ofs <<= 1) {
        int u = (t >= ofs) ? sd[t - ofs] : 0;
        __syncthreads();
        v += u;
        sd[t] = v;
        __syncthreads();
    }
    if (i < n) {
        int rs = soff + (v - dg);           // global exclusive prefix
        g_rowstart[i] = rs;
        g_fill[i]     = rs;
        g_dinv[i]     = rsqrtf((float)(dg + 1));
        g_degi[i]     = 0;                  // reset for next graph replay
    }
    if (bid == 0 && t == 0) g_rowstart[n] = E;
}

// ---------------------------------------------------------------------------
// K3 (fused): heterogeneous launch.
//   blocks [0, nGemm)          : xsh = fp16( (x@W) * dinv[row] )
//   blocks [nGemm, nGemm+nFill): CSR fill (2 edges/thread via int2)
// fill and gemm are independent (both depend only on scan3) and run
// concurrently in one launch: cost ~= max(fill, gemm) instead of sum.
// ---------------------------------------------------------------------------
__device__ __forceinline__ void gemm_body(
    const float* __restrict__ x, const float* __restrict__ W,
    int n, int gemmBid)
{
    __shared__ float  sX[64][68];
    __shared__ float4 sW[64][16];

    const int t = threadIdx.x;
    const int rowBase = gemmBid * 64;

    {
        const float4* W4 = (const float4*)W;
        #pragma unroll
        for (int i = 0; i < 4; i++) {
            int idx = t + i * 256;
            sW[idx >> 4][idx & 15] = W4[idx];
        }
    }
    {
        #pragma unroll
        for (int i = 0; i < 4; i++) {
            int idx = t + i * 256;
            int r = idx >> 4, c4 = idx & 15;
            int row = rowBase + r;
            float4 v = make_float4(0.f, 0.f, 0.f, 0.f);
            if (row < n) v = ((const float4*)(x + (size_t)row * D))[c4];
            *(float4*)&sX[r][c4 * 4] = v;
        }
    }
    __syncthreads();

    const int c4 = t & 15;
    const int r0 = t >> 4;

    float4 acc[4];
    #pragma unroll
    for (int r = 0; r < 4; r++) acc[r] = make_float4(0.f, 0.f, 0.f, 0.f);

    #pragma unroll
    for (int k = 0; k < 64; k += 4) {
        float4 w0 = sW[k + 0][c4];
        float4 w1 = sW[k + 1][c4];
        float4 w2 = sW[k + 2][c4];
        float4 w3 = sW[k + 3][c4];
        #pragma unroll
        for (int r = 0; r < 4; r++) {
            float4 xv = *(const float4*)&sX[r0 + 16 * r][k];
            acc[r].x += xv.x * w0.x + xv.y * w1.x + xv.z * w2.x + xv.w * w3.x;
            acc[r].y += xv.x * w0.y + xv.y * w1.y + xv.z * w2.y + xv.w * w3.y;
            acc[r].z += xv.x * w0.z + xv.y * w1.z + xv.z * w2.z + xv.w * w3.z;
            acc[r].w += xv.x * w0.w + xv.y * w1.w + xv.z * w2.w + xv.w * w3.w;
        }
    }

    #pragma unroll
    for (int r = 0; r < 4; r++) {
        int row = rowBase + r0 + 16 * r;
        if (row < n) {
            float di = g_dinv[row];
            __half2* hp = (__half2*)(g_xsh + (size_t)row * D);
            hp[c4 * 2 + 0] = __floats2half2_rn(acc[r].x * di, acc[r].y * di);
            hp[c4 * 2 + 1] = __floats2half2_rn(acc[r].z * di, acc[r].w * di);
        }
    }
}

__device__ __forceinline__ void fill_body(
    const int* __restrict__ ei, int E, int fillBid)
{
    int g = fillBid * 256 + threadIdx.x;
    int e0 = 2 * g;
    if (e0 + 1 < E) {
        int2 ss = *(const int2*)&ei[e0];
        int2 dd = *(const int2*)&ei[E + e0];
        int p0 = atomicAdd(&g_fill[dd.x], 1);
        int p1 = atomicAdd(&g_fill[dd.y], 1);
        g_srclist[p0] = ss.x;
        g_srclist[p1] = ss.y;
    } else if (e0 < E) {
        int s = __ldg(&ei[e0]);
        int d = __ldg(&ei[E + e0]);
        int pos = atomicAdd(&g_fill[d], 1);
        g_srclist[pos] = s;
    }
}

__global__ void __launch_bounds__(256) fused_fill_gemm_kernel(
    const float* __restrict__ x, const float* __restrict__ W,
    const int* __restrict__ ei, int E, int n, int nGemm)
{
    if ((int)blockIdx.x < nGemm) {
        gemm_body(x, W, n, blockIdx.x);
    } else {
        fill_body(ei, E, blockIdx.x - nGemm);
    }
}

// ---------------------------------------------------------------------------
// K4: CSR gather, warp per node, MLP=8 (proven best config).
//   out[i] = ( xsh[i] + sum_{s in in(i)} xsh[s] ) * dinv[i] + b
// ---------------------------------------------------------------------------
__global__ void __launch_bounds__(256) gather_kernel(
    const float* __restrict__ b, float* __restrict__ out, int n)
{
    int warp = (int)((blockIdx.x * 256u + threadIdx.x) >> 5);
    int lane = threadIdx.x & 31;
    if (warp >= n) return;
    const int i = warp;

    const __half2* __restrict__ xbase = (const __half2*)g_xsh;

    int start = g_rowstart[i];
    int cnt   = g_rowstart[i + 1] - start;
    float di  = g_dinv[i];

    // self message (fp16 row); row stride in __half2 units = D/2 = 32
    float2 acc = __half22float2(__ldg(xbase + (size_t)i * 32 + lane));

    for (int k0 = 0; k0 < cnt; k0 += 32) {
        int m = min(cnt - k0, 32);
        int sl = (lane < m) ? __ldg(&g_srclist[start + k0 + lane]) : 0;

        int kk = 0;
        for (; kk + 8 <= m; kk += 8) {
            int s0 = __shfl_sync(0xFFFFFFFFu, sl, kk + 0);
            int s1 = __shfl_sync(0xFFFFFFFFu, sl, kk + 1);
            int s2 = __shfl_sync(0xFFFFFFFFu, sl, kk + 2);
            int s3 = __shfl_sync(0xFFFFFFFFu, sl, kk + 3);
            int s4 = __shfl_sync(0xFFFFFFFFu, sl, kk + 4);
            int s5 = __shfl_sync(0xFFFFFFFFu, sl, kk + 5);
            int s6 = __shfl_sync(0xFFFFFFFFu, sl, kk + 6);
            int s7 = __shfl_sync(0xFFFFFFFFu, sl, kk + 7);
            // 8 independent 128B row loads in flight
            __half2 v0 = __ldg(xbase + (size_t)s0 * 32 + lane);
            __half2 v1 = __ldg(xbase + (size_t)s1 * 32 + lane);
            __half2 v2 = __ldg(xbase + (size_t)s2 * 32 + lane);
            __half2 v3 = __ldg(xbase + (size_t)s3 * 32 + lane);
            __half2 v4 = __ldg(xbase + (size_t)s4 * 32 + lane);
            __half2 v5 = __ldg(xbase + (size_t)s5 * 32 + lane);
            __half2 v6 = __ldg(xbase + (size_t)s6 * 32 + lane);
            __half2 v7 = __ldg(xbase + (size_t)s7 * 32 + lane);
            float2 f;
            f = __half22float2(v0); acc.x += f.x; acc.y += f.y;
            f = __half22float2(v1); acc.x += f.x; acc.y += f.y;
            f = __half22float2(v2); acc.x += f.x; acc.y += f.y;
            f = __half22float2(v3); acc.x += f.x; acc.y += f.y;
            f = __half22float2(v4); acc.x += f.x; acc.y += f.y;
            f = __half22float2(v5); acc.x += f.x; acc.y += f.y;
            f = __half22float2(v6); acc.x += f.x; acc.y += f.y;
            f = __half22float2(v7); acc.x += f.x; acc.y += f.y;
        }
        for (; kk < m; kk++) {
            int s = __shfl_sync(0xFFFFFFFFu, sl, kk);
            float2 f = __half22float2(__ldg(xbase + (size_t)s * 32 + lane));
            acc.x += f.x; acc.y += f.y;
        }
    }

    float2 bb = *((const float2*)b + lane);
    float2 o;
    o.x = acc.x * di + bb.x;
    o.y = acc.y * di + bb.y;
    *((float2*)(out + (size_t)i * D) + lane) = o;
}

// ---------------------------------------------------------------------------
// Launch
// Inputs (metadata order): x [n*64] f32, edge_index [2*E] int32, W [64*64] f32,
//                          b [64] f32. Output: [n*64] f32.
// 5 launches: deg, scan1, scan3, fused(fill || gemm), gather.
// ---------------------------------------------------------------------------
extern "C" void kernel_launch(void* const* d_in, const int* in_sizes, int n_in,
                              void* d_out, int out_size)
{
    const float* x  = (const float*)d_in[0];
    const int*   ei = (const int*)d_in[1];
    const float* W  = (const float*)d_in[2];
    const float* b  = (const float*)d_in[3];
    float*       out = (float*)d_out;

    const int n = in_sizes[0] / D;       // 100000
    const int E = in_sizes[1] / 2;       // 1600000
    const int nblocks = (n + 255) / 256; // 391

    {
        int pairs = (E + 1) / 2;
        deg_count_kernel<<<(pairs + 255) / 256, 256>>>(ei + E, E);
    }
    scan1_kernel<<<nblocks, 256>>>(n);
    scan3_kernel<<<nblocks, 256>>>(n, E);
    {
        int nGemm = (n + 63) / 64;                     // 1563
        int pairs = (E + 1) / 2;
        int nFill = (pairs + 255) / 256;               // 3125
        fused_fill_gemm_kernel<<<nGemm + nFill, 256>>>(x, W, ei, E, n, nGemm);
    }
    {
        int total = n * 32;                            // 1 warp per node
        gather_kernel<<<(total + 255) / 256, 256>>>(b, out, n);
    }
}